// round 9
// baseline (speedup 1.0000x reference)
#include <cuda_runtime.h>

#define HID 10
#define ROWF 2048                  // floats per row
#define NCONS 20                   // consumer warps
#define WARPS 21                   // + 1 producer warp
#define THREADS (WARPS * 32)
#define NBUF 26                    // ring slots (8KB each)
#define KINF 6                     // cp.async groups kept in flight

// dynamic smem layout (floats)
#define RING_F   (NBUF * 2048)
#define AQ_OFF   RING_F                    // 160 ull = 320 floats
#define BQ_OFF   (AQ_OFF + 320)            // 176 ull = 352 floats
#define EPI_OFF  (BQ_OFF + 352)            // 20 floats
#define BAR_OFF  (EPI_OFF + 20)            // 2*NBUF mbarriers (8B each) = 4*NBUF floats
#define SMEM_FLOATS (BAR_OFF + 4 * NBUF)
#define SMEM_BYTES  (SMEM_FLOATS * 4)

typedef unsigned long long ull;

__device__ __forceinline__ void fma2(ull& acc, ull a, ull b) {
    asm("fma.rn.f32x2 %0, %1, %2, %0;" : "+l"(acc) : "l"(a), "l"(b));
}
__device__ __forceinline__ float2 unp(ull v) {
    float2 r; asm("mov.b64 {%0,%1}, %2;" : "=f"(r.x), "=f"(r.y) : "l"(v)); return r;
}
__device__ __forceinline__ ull pk(float lo, float hi) {
    ull v; asm("mov.b64 %0, {%1,%2};" : "=l"(v) : "f"(lo), "f"(hi)); return v;
}
__device__ __forceinline__ void cpa16(unsigned dst, const void* src) {
    asm volatile("cp.async.cg.shared.global [%0], [%1], 16;" :: "r"(dst), "l"(src));
}
__device__ __forceinline__ unsigned s2u(const void* p) {
    unsigned a;
    asm("{ .reg .u64 t; cvta.to.shared.u64 t, %1; cvt.u32.u64 %0, t; }" : "=r"(a) : "l"(p));
    return a;
}
__device__ __forceinline__ void mbar_init(unsigned a, unsigned cnt) {
    asm volatile("mbarrier.init.shared.b64 [%0], %1;" :: "r"(a), "r"(cnt) : "memory");
}
__device__ __forceinline__ void mbar_arrive(unsigned a) {
    asm volatile("mbarrier.arrive.release.cta.shared::cta.b64 _, [%0];" :: "r"(a) : "memory");
}
__device__ __forceinline__ void mbar_wait(unsigned a, unsigned par) {
    asm volatile(
        "{ .reg .pred P;\n"
        "W%=:\n"
        " mbarrier.try_wait.parity.acquire.cta.shared::cta.b64 P, [%0], %1, 0x989680;\n"
        " @P bra D%=;\n"
        " bra W%=;\n"
        "D%=: }"
        :: "r"(a), "r"(par) : "memory");
}

__global__ __launch_bounds__(THREADS, 1)
void iin_kernel(const float* __restrict__ outputs,
                const int* __restrict__ tests32,
                const long long* __restrict__ tests64,
                const float* __restrict__ W1,
                const float* __restrict__ b1,
                const float* __restrict__ W2,
                float* __restrict__ out,
                int B)
{
    extern __shared__ float smem[];
    ull*   aQ  = (ull*)(smem + AQ_OFF);   // [t2*20 + sub*10 + j] : f32x2(W1[32+4t2+2sub][j], W1[33+..][j])
    ull*   bQ  = (ull*)(smem + BQ_OFF);   // [q*22  + sub*10 + j] : person-half, stride 22 (conflict-free)
    float* epi = smem + EPI_OFF;          // w2[0..9], b1[10..19]

    const int tid  = threadIdx.x;
    const unsigned lane = tid & 31;
    const int warp = tid >> 5;

    const unsigned ringu = s2u(smem);
    const unsigned baru  = s2u(smem + BAR_OFF);
    // full[i] = baru + 16*i ; empty[i] = baru + 16*i + 8

    for (int idx = tid; idx < 160; idx += THREADS) {
        int t2 = idx / 20, r = idx % 20, sub = r / 10, j = r % 10;
        int d0 = 32 + 4 * t2 + 2 * sub;
        aQ[t2 * 20 + sub * 10 + j] = pk(W1[d0 * HID + j], W1[(d0 + 1) * HID + j]);
        int e0 = 4 * t2 + 2 * sub;
        bQ[t2 * 22 + sub * 10 + j] = pk(W1[e0 * HID + j], W1[(e0 + 1) * HID + j]);
    }
    if (tid < 10) { epi[tid] = W2[tid]; epi[tid + 10] = b1[tid]; }
    if (tid == 0) {
        for (int i = 0; i < NBUF; ++i) {
            mbar_init(baru + 16 * i, 1);       // full: producer lane0
            mbar_init(baru + 16 * i + 8, 1);   // empty: consumer lane0
        }
    }
    __syncthreads();

    // tests dtype probe: int64 -> every odd int32 word is a zero high-half
    int pidx = 2 * (int)lane + 1; if (pidx > 2 * B - 1) pidx = 2 * B - 1;
    const bool idx32 = __any_sync(0xffffffffu, tests32[pidx] != 0);

    const int b = blockIdx.x, G = gridDim.x;
    const int S = (B - 1 - b) / G + 1;          // rows streamed by this block

    if (warp == NCONS) {
        // ================= PRODUCER =================
        unsigned dsto[16];
#pragma unroll
        for (int u = 0; u < 16; ++u) {
            unsigned c = lane + 32u * (unsigned)u, w = c >> 3, k = c & 7u;
            dsto[u] = (8u * w + (k ^ (w & 7u))) * 16u;
        }
        for (int s = 0; s < S; ++s) {
            int slot = s % NBUF;
            if (s >= NBUF) mbar_wait(baru + 16 * slot + 8, (unsigned)((s / NBUF - 1) & 1));
            const char* src = (const char*)(outputs + (size_t)(b + s * G) * ROWF)
                              + (size_t)lane * 16u;
            unsigned dstb = ringu + (unsigned)slot * 8192u;
#pragma unroll
            for (int u = 0; u < 16; ++u) cpa16(dstb + dsto[u], src + 512u * u);
            asm volatile("cp.async.commit_group;");
            if (s >= KINF) {
                asm volatile("cp.async.wait_group %0;" :: "n"(KINF));
                if (lane == 0) mbar_arrive(baru + 16 * ((s - KINF) % NBUF));
            }
        }
        asm volatile("cp.async.wait_group 0;");
        if (lane == 0) {
            int s0 = S - KINF; if (s0 < 0) s0 = 0;
            for (int s = s0; s < S; ++s) mbar_arrive(baru + 16 * (s % NBUF));
        }
    } else {
        // ================= CONSUMERS =================
        const unsigned q = lane & 7u;
        const double2* bp2 = (const double2*)(bQ + q * 22);

        for (int s = warp; s < S; s += NCONS) {
            int slot = s % NBUF;
            int row  = b + s * G;
            int person, loc;
            if (idx32) { person = tests32[2 * row];      loc = tests32[2 * row + 1]; }
            else       { person = (int)tests64[2 * row]; loc = (int)tests64[2 * row + 1]; }

            mbar_wait(baru + 16 * slot, (unsigned)((s / NBUF) & 1));

            const double2* rp = (const double2*)(smem + slot * 2048);

            // ---- person partial: 8-lane groups, member q handles d = 4q..4q+3 ----
            double2 pvc = rp[8u * (unsigned)person + (q ^ ((unsigned)person & 7u))];
            ull xp01 = __double_as_longlong(pvc.x), xp23 = __double_as_longlong(pvc.y);
            ull s2[HID];
#pragma unroll
            for (int j = 0; j < HID; ++j) s2[j] = 0ULL;
#pragma unroll
            for (int jj = 0; jj < 5; ++jj) {
                double2 B0 = bp2[jj], B1 = bp2[jj + 5];
                fma2(s2[2 * jj],     xp01, __double_as_longlong(B0.x));
                fma2(s2[2 * jj + 1], xp01, __double_as_longlong(B0.y));
                fma2(s2[2 * jj],     xp23, __double_as_longlong(B1.x));
                fma2(s2[2 * jj + 1], xp23, __double_as_longlong(B1.y));
            }
            float pb[HID];
#pragma unroll
            for (int j = 0; j < HID; ++j) { float2 f = unp(s2[j]); pb[j] = f.x + f.y; }
#pragma unroll
            for (int off = 4; off; off >>= 1)
#pragma unroll
                for (int j = 0; j < HID; ++j)
                    pb[j] += __shfl_xor_sync(0xffffffffu, pb[j], off);
#pragma unroll
            for (int j = 0; j < HID; ++j) pb[j] += epi[10 + j];

            // ---- main loop: 2 wires/lane, weights shared across both ----
            ull a0[HID], a1[HID];
#pragma unroll
            for (int j = 0; j < HID; ++j) { a0[j] = 0ULL; a1[j] = 0ULL; }
#pragma unroll
            for (int t2 = 0; t2 < 8; ++t2) {
                double2 xa = rp[8u * lane        + ((unsigned)t2 ^ (lane & 7u))];
                double2 xb = rp[8u * (lane + 32) + ((unsigned)t2 ^ (lane & 7u))];
                ull xa01 = __double_as_longlong(xa.x), xa23 = __double_as_longlong(xa.y);
                ull xb01 = __double_as_longlong(xb.x), xb23 = __double_as_longlong(xb.y);
                const double2* ap = (const double2*)(aQ + t2 * 20);
#pragma unroll
                for (int jj = 0; jj < 5; ++jj) {
                    double2 A0 = ap[jj], A1 = ap[jj + 5];
                    ull A0x = __double_as_longlong(A0.x), A0y = __double_as_longlong(A0.y);
                    ull A1x = __double_as_longlong(A1.x), A1y = __double_as_longlong(A1.y);
                    fma2(a0[2 * jj],     xa01, A0x); fma2(a0[2 * jj + 1], xa01, A0y);
                    fma2(a0[2 * jj],     xa23, A1x); fma2(a0[2 * jj + 1], xa23, A1y);
                    fma2(a1[2 * jj],     xb01, A0x); fma2(a1[2 * jj + 1], xb01, A0y);
                    fma2(a1[2 * jj],     xb23, A1x); fma2(a1[2 * jj + 1], xb23, A1y);
                }
            }

            // done reading the slot
            __syncwarp();
            if (lane == 0) mbar_arrive(baru + 16 * slot + 8);

            // ---- logits (b2 cancels in lse - logit) ----
            float lg0 = 0.f, lg1 = 0.f;
#pragma unroll
            for (int j = 0; j < HID; ++j) {
                float2 f0 = unp(a0[j]), f1 = unp(a1[j]);
                float q0 = fmaxf(f0.x + f0.y + pb[j], 0.f);
                float q1 = fmaxf(f1.x + f1.y + pb[j], 0.f);
                lg0 = fmaf(q0, epi[j], lg0);
                lg1 = fmaf(q1, epi[j], lg1);
            }

            // ---- log-softmax over 64 wires ----
            float m = fmaxf(lg0, lg1);
#pragma unroll
            for (int off = 16; off; off >>= 1)
                m = fmaxf(m, __shfl_xor_sync(0xffffffffu, m, off));
            float sm_ = __expf(lg0 - m) + __expf(lg1 - m);
#pragma unroll
            for (int off = 16; off; off >>= 1)
                sm_ += __shfl_xor_sync(0xffffffffu, sm_, off);
            float lse = m + __logf(sm_);

            float sel = (loc >= 32) ? lg1 : lg0;
            float lv  = __shfl_sync(0xffffffffu, sel, loc & 31);
            if (lane == 0) out[row] = lse - lv;
        }
    }
}

extern "C" void kernel_launch(void* const* d_in, const int* in_sizes, int n_in,
                              void* d_out, int out_size)
{
    const float* outputs = (const float*)d_in[0];
    const void*  tests   = d_in[1];
    const float* W1      = (const float*)d_in[2];
    const float* b1      = (const float*)d_in[3];
    const float* W2      = (const float*)d_in[4];
    float*       out     = (float*)d_out;

    int B = in_sizes[0] / ROWF;   // 8192

    int sm = 0;
    cudaDeviceGetAttribute(&sm, cudaDevAttrMultiProcessorCount, 0);
    if (sm <= 0) sm = 148;
    cudaFuncSetAttribute(iin_kernel, cudaFuncAttributeMaxDynamicSharedMemorySize, SMEM_BYTES);

    iin_kernel<<<sm, THREADS, SMEM_BYTES>>>(
        outputs, (const int*)tests, (const long long*)tests, W1, b1, W2, out, B);
}